// round 14
// baseline (speedup 1.0000x reference)
#include <cuda_runtime.h>
#include <math.h>
#include <stdint.h>

// Problem constants
#define B_  256
#define S_  256
#define H_  512
#define H2_ 1024
#define O_  512

// ---------------------------------------------------------------------------
// Scratch (device globals)
// ---------------------------------------------------------------------------
__device__ float g_Gx  [(size_t)S_ * B_ * H2_];
__device__ float g_Cx  [(size_t)S_ * B_ * H_ ];
__device__ float g_h   [B_ * H_];
__device__ float g_z   [B_ * H_];

// pre-split bf16 hi/lo packed pairs
__device__ unsigned g_xeh [(size_t)S_ * B_ * H_ / 2];   // xe (A of pre-GEMMs)
__device__ unsigned g_xel [(size_t)S_ * B_ * H_ / 2];
__device__ unsigned g_hallh[(size_t)S_ * B_ * H_ / 2];  // hidden history (A of ys GEMM)
__device__ unsigned g_halll[(size_t)S_ * B_ * H_ / 2];
__device__ unsigned g_hh [B_ * H_ / 2];                 // current h
__device__ unsigned g_hl [B_ * H_ / 2];
__device__ unsigned g_rhh[B_ * H_ / 2];                 // r*h
__device__ unsigned g_rhl[B_ * H_ / 2];
__device__ unsigned g_Wgh[1024 * 256], g_Wgl[1024 * 256];  // Wg[:, :H]
__device__ unsigned g_Whh2[512 * 256], g_Whl2[512 * 256];  // Wh[:, :H]
__device__ unsigned g_Woh[512 * 256],  g_Wol[512 * 256];   // Wo

__device__ unsigned g_gcnt[8 * 32];   // group barrier counters (128B apart)

// ---------------------------------------------------------------------------
// helpers
// ---------------------------------------------------------------------------
__device__ __forceinline__ float sigm(float x) {
    return __fdividef(1.0f, 1.0f + __expf(-x));
}
__device__ __forceinline__ float tanh_fast(float x) {
    return 1.0f - 2.0f * __fdividef(1.0f, __expf(2.0f * x) + 1.0f);
}

// pack (f0,f1) -> bf16x2 hi word {lo=f0, hi=f1}; lo word = residuals
__device__ __forceinline__ void cvt_pair(float f0, float f1,
                                         unsigned& hi2, unsigned& lo2) {
    asm("cvt.rn.bf16x2.f32 %0, %2, %1;" : "=r"(hi2) : "f"(f0), "f"(f1));
    float h0 = __uint_as_float(hi2 << 16);
    float h1 = __uint_as_float(hi2 & 0xFFFF0000u);
    float l0 = f0 - h0, l1 = f1 - h1;
    asm("cvt.rn.bf16x2.f32 %0, %2, %1;" : "=r"(lo2) : "f"(l0), "f"(l1));
}

__device__ __forceinline__ void mma16816(float* c,
                                         unsigned a0, unsigned a1,
                                         unsigned a2, unsigned a3,
                                         unsigned b0, unsigned b1) {
    asm volatile(
        "mma.sync.aligned.m16n8k16.row.col.f32.bf16.bf16.f32 "
        "{%0,%1,%2,%3}, {%4,%5,%6,%7}, {%8,%9}, {%0,%1,%2,%3};"
        : "+f"(c[0]), "+f"(c[1]), "+f"(c[2]), "+f"(c[3])
        : "r"(a0), "r"(a1), "r"(a2), "r"(a3), "r"(b0), "r"(b1));
}

// ---------------------------------------------------------------------------
// Group barrier (16 blocks/group): REDG arrival + monotonic count wait
// ---------------------------------------------------------------------------
__device__ __forceinline__ void group_sync(int grp, unsigned target) {
    __threadfence();
    __syncthreads();
    if (threadIdx.x == 0) {
        unsigned* cp = &g_gcnt[grp * 32];
        asm volatile("red.global.gpu.add.u32 [%0], %1;"
                     :: "l"(cp), "r"(1u) : "memory");
        unsigned v;
        do {
            asm volatile("ld.acquire.gpu.u32 %0, [%1];" : "=r"(v) : "l"(cp));
        } while (v < target);
    }
    __syncthreads();
}

// ---------------------------------------------------------------------------
// split_weights: one-shot fp32 -> bf16 hi/lo for the big-GEMM weights
// rows: [0,1024) Wg[:, :H]; [1024,1536) Wh[:, :H]; [1536,2048) Wo
// ---------------------------------------------------------------------------
__global__ void split_weights(const float* __restrict__ Wg,
                              const float* __restrict__ Wh,
                              const float* __restrict__ Wo) {
    int idx = blockIdx.x * 256 + threadIdx.x;   // 2048 * 128
    int rid = idx >> 7;
    int kq  = idx & 127;
    const float* src;
    unsigned *dh, *dl;
    if (rid < 1024) {
        src = Wg + (size_t)rid * H2_ + kq * 4;
        dh = g_Wgh + rid * 256 + kq * 2;  dl = g_Wgl + rid * 256 + kq * 2;
    } else if (rid < 1536) {
        int r = rid - 1024;
        src = Wh + (size_t)r * H2_ + kq * 4;
        dh = g_Whh2 + r * 256 + kq * 2;   dl = g_Whl2 + r * 256 + kq * 2;
    } else {
        int r = rid - 1536;
        src = Wo + (size_t)r * H_ + kq * 4;
        dh = g_Woh + r * 256 + kq * 2;    dl = g_Wol + r * 256 + kq * 2;
    }
    float4 v = *(const float4*)src;
    unsigned h0, l0, h1, l1;
    cvt_pair(v.x, v.y, h0, l0);
    cvt_pair(v.z, v.w, h1, l1);
    *(uint2*)dh = make_uint2(h0, h1);
    *(uint2*)dl = make_uint2(l0, l1);
}

// ---------------------------------------------------------------------------
// Tensor-core big GEMM, pre-split inputs: C[65536,N] = A @ B^T + bias
// A/B are bf16 hi/lo global arrays, 256 uints per row (K=512).
// 128x128 block, 8 warps (warp = 32m x 64n), 32-k chunks, split-3 mma.
// ---------------------------------------------------------------------------
#define TSTR 80   // smem row stride bytes (32 bf16 = 64B data + 16B pad)

__global__ __launch_bounds__(256, 2)
void sgemm_tc2(int Asel, int Bsel, const float* __restrict__ bias, int mode,
               float* __restrict__ yout) {
    __shared__ char sAH[128 * TSTR];
    __shared__ char sAL[128 * TSTR];
    __shared__ char sBH[128 * TSTR];
    __shared__ char sBL[128 * TSTR];

    const int tid  = threadIdx.x;
    const int wid  = tid >> 5;
    const int lane = tid & 31;
    const int g    = lane >> 2;
    const int tg   = lane & 3;
    const int wm   = wid >> 1;
    const int wn   = wid & 1;
    const int m0   = blockIdx.y * 128;
    const int n0   = blockIdx.x * 128;

    const unsigned* Ah = Asel ? g_hallh : g_xeh;
    const unsigned* Al = Asel ? g_halll : g_xel;
    const unsigned* Bh = (Bsel == 0) ? g_Wgh : (Bsel == 1 ? g_Whh2 : g_Woh);
    const unsigned* Bl = (Bsel == 0) ? g_Wgl : (Bsel == 1 ? g_Whl2 : g_Wol);

    const int lr = tid >> 1;
    const int lh = tid & 1;
    const unsigned* Aph = Ah + (size_t)(m0 + lr) * 256 + lh * 8;
    const unsigned* Apl = Al + (size_t)(m0 + lr) * 256 + lh * 8;
    const unsigned* Bph = Bh + (size_t)(n0 + lr) * 256 + lh * 8;
    const unsigned* Bpl = Bl + (size_t)(n0 + lr) * 256 + lh * 8;
    const size_t dA = (size_t)(lr * TSTR + lh * 32);

    float c[2][8][4];
    #pragma unroll
    for (int i = 0; i < 2; i++)
        #pragma unroll
        for (int j = 0; j < 8; j++)
            #pragma unroll
            for (int q = 0; q < 4; q++) c[i][j][q] = 0.f;

    #pragma unroll 1
    for (int it = 0; it < 16; it++) {
        const int kb = it * 16;       // uint offset of this 32-k chunk
        uint4 vah = *(const uint4*)(Aph + kb);
        uint4 vah2 = *(const uint4*)(Aph + kb + 4);
        uint4 val = *(const uint4*)(Apl + kb);
        uint4 val2 = *(const uint4*)(Apl + kb + 4);
        uint4 vbh = *(const uint4*)(Bph + kb);
        uint4 vbh2 = *(const uint4*)(Bph + kb + 4);
        uint4 vbl = *(const uint4*)(Bpl + kb);
        uint4 vbl2 = *(const uint4*)(Bpl + kb + 4);
        *(uint4*)(sAH + dA)      = vah;
        *(uint4*)(sAH + dA + 16) = vah2;
        *(uint4*)(sAL + dA)      = val;
        *(uint4*)(sAL + dA + 16) = val2;
        *(uint4*)(sBH + dA)      = vbh;
        *(uint4*)(sBH + dA + 16) = vbh2;
        *(uint4*)(sBL + dA)      = vbl;
        *(uint4*)(sBL + dA + 16) = vbl2;
        __syncthreads();

        #pragma unroll
        for (int s = 0; s < 2; s++) {
            unsigned aH[2][4], aL[2][4];
            #pragma unroll
            for (int mt = 0; mt < 2; mt++) {
                int ab = (wm * 32 + mt * 16 + g) * TSTR + tg * 4 + s * 32;
                aH[mt][0] = *(const unsigned*)(sAH + ab);
                aH[mt][1] = *(const unsigned*)(sAH + ab + 8 * TSTR);
                aH[mt][2] = *(const unsigned*)(sAH + ab + 16);
                aH[mt][3] = *(const unsigned*)(sAH + ab + 8 * TSTR + 16);
                aL[mt][0] = *(const unsigned*)(sAL + ab);
                aL[mt][1] = *(const unsigned*)(sAL + ab + 8 * TSTR);
                aL[mt][2] = *(const unsigned*)(sAL + ab + 16);
                aL[mt][3] = *(const unsigned*)(sAL + ab + 8 * TSTR + 16);
            }
            #pragma unroll
            for (int nt2 = 0; nt2 < 8; nt2++) {
                int nb = (wn * 64 + nt2 * 8 + g) * TSTR + tg * 4 + s * 32;
                unsigned bh0 = *(const unsigned*)(sBH + nb);
                unsigned bh1 = *(const unsigned*)(sBH + nb + 16);
                unsigned bl0 = *(const unsigned*)(sBL + nb);
                unsigned bl1 = *(const unsigned*)(sBL + nb + 16);
                #pragma unroll
                for (int mt = 0; mt < 2; mt++) {
                    mma16816(c[mt][nt2], aH[mt][0], aH[mt][1], aH[mt][2], aH[mt][3], bh0, bh1);
                    mma16816(c[mt][nt2], aH[mt][0], aH[mt][1], aH[mt][2], aH[mt][3], bl0, bl1);
                    mma16816(c[mt][nt2], aL[mt][0], aL[mt][1], aL[mt][2], aL[mt][3], bh0, bh1);
                }
            }
        }
        __syncthreads();
    }

    #pragma unroll
    for (int mt = 0; mt < 2; mt++) {
        int row0 = m0 + wm * 32 + mt * 16 + g;
        int row1 = row0 + 8;
        #pragma unroll
        for (int nt2 = 0; nt2 < 8; nt2++) {
            int n = n0 + wn * 64 + nt2 * 8 + tg * 2;
            float2 bv = *(const float2*)(bias + n);
            float o00 = c[mt][nt2][0] + bv.x, o01 = c[mt][nt2][1] + bv.y;
            float o10 = c[mt][nt2][2] + bv.x, o11 = c[mt][nt2][3] + bv.y;
            if (mode == 0) {
                *(float2*)(g_Gx + (size_t)row0 * H2_ + n) = make_float2(o00, o01);
                *(float2*)(g_Gx + (size_t)row1 * H2_ + n) = make_float2(o10, o11);
            } else if (mode == 1) {
                *(float2*)(g_Cx + (size_t)row0 * H_ + n) = make_float2(o00, o01);
                *(float2*)(g_Cx + (size_t)row1 * H_ + n) = make_float2(o10, o11);
            } else {
                int s0 = row0 >> 8, b0i = row0 & 255;
                int s1 = row1 >> 8, b1i = row1 & 255;
                *(float2*)(yout + ((size_t)b0i * S_ + s0) * O_ + n) = make_float2(o00, o01);
                *(float2*)(yout + ((size_t)b1i * S_ + s1) * O_ + n) = make_float2(o10, o11);
            }
        }
    }
}

// ---------------------------------------------------------------------------
// Persistent recurrent kernel: R11 fragments + pre-split state fills +
// split-3 independent accumulators. 128 blocks x 256 threads, groups of 16.
//   gate: m [mt*32,+32) x n [nt*64,+64) of 1024; warp = m16 x n16
//   cand: m [mt*32,+32) x n [nt*32,+32) of 512;  warp = m16 x n8
// ---------------------------------------------------------------------------
#define WROW 1040
#define AROW 272
#define SM_WGH 0
#define SM_WGL (SM_WGH + 64 * WROW)
#define SM_WHH (SM_WGL + 64 * WROW)
#define SM_WHL (SM_WHH + 32 * WROW)
#define SM_AH  (SM_WHL + 32 * WROW)     // 199680
#define SM_AL  (SM_AH + 32 * AROW)      // 208384
#define GRU_SMEM (SM_AL + 32 * AROW)    // 217088

__global__ __launch_bounds__(256, 1)
void gru_persist(const float* __restrict__ Wg, const float* __restrict__ Wh) {
    extern __shared__ char smc[];

    const int tid  = threadIdx.x;
    const int bid  = blockIdx.x;
    const int mt   = bid >> 4;
    const int nt   = bid & 15;
    const int wid  = tid >> 5;
    const int lane = tid & 31;
    const int wm   = wid >> 2;
    const int wn   = wid & 3;
    const int g    = lane >> 2;
    const int tg   = lane & 3;

    // zero fp32 h + split h
    {
        int base = (bid * 256 + tid) * 4;
        *(float4*)&g_h[base] = make_float4(0.f, 0.f, 0.f, 0.f);
        int gid = bid * 256 + tid;
        *(uint2*)&g_hh[gid * 2] = make_uint2(0u, 0u);
        *(uint2*)&g_hl[gid * 2] = make_uint2(0u, 0u);
    }

    {   // Wg recurrent half split: 64 rows (nt*64+j), k in [512,1024)
        int j  = tid >> 2;
        int ks = (tid & 3) * 128;
        const float* src = Wg + (size_t)(nt * 64 + j) * H2_ + H_ + ks;
        char* dh = smc + SM_WGH + j * WROW + ks * 2;
        char* dl = smc + SM_WGL + j * WROW + ks * 2;
        #pragma unroll 8
        for (int q = 0; q < 32; q++) {
            float4 v = *(const float4*)(src + q * 4);
            unsigned h0, l0, h1, l1;
            cvt_pair(v.x, v.y, h0, l0);
            cvt_pair(v.z, v.w, h1, l1);
            *(uint2*)(dh + q * 8) = make_uint2(h0, h1);
            *(uint2*)(dl + q * 8) = make_uint2(l0, l1);
        }
    }
    {   // Wh recurrent half split: 32 rows (nt*32+j), k in [512,1024)
        int j  = tid >> 3;
        int ks = (tid & 7) * 64;
        const float* src = Wh + (size_t)(nt * 32 + j) * H2_ + H_ + ks;
        char* dh = smc + SM_WHH + j * WROW + ks * 2;
        char* dl = smc + SM_WHL + j * WROW + ks * 2;
        #pragma unroll 8
        for (int q = 0; q < 16; q++) {
            float4 v = *(const float4*)(src + q * 4);
            unsigned h0, l0, h1, l1;
            cvt_pair(v.x, v.y, h0, l0);
            cvt_pair(v.z, v.w, h1, l1);
            *(uint2*)(dh + q * 8) = make_uint2(h0, h1);
            *(uint2*)(dl + q * 8) = make_uint2(l0, l1);
        }
    }
    unsigned tgt = 0;
    group_sync(mt, tgt += 16);

    // panel-fill coords (row = lane of fill-warp -> conflict-free STS.128)
    const int pr = tid & 31;
    const int pq = tid >> 5;
    const unsigned* hhrow  = g_hh  + (size_t)(mt * 32 + pr) * 256 + pq * 8;
    const unsigned* hlrow  = g_hl  + (size_t)(mt * 32 + pr) * 256 + pq * 8;
    const unsigned* rhhrow = g_rhh + (size_t)(mt * 32 + pr) * 256 + pq * 8;
    const unsigned* rhlrow = g_rhl + (size_t)(mt * 32 + pr) * 256 + pq * 8;
    char* stsH = smc + SM_AH + pr * AROW + pq * 32;
    char* stsL = smc + SM_AL + pr * AROW + pq * 32;

    // fragment bases (R11 proven mapping)
    const int aHb  = SM_AH  + (wm * 16 + g) * AROW + tg * 4;
    const int aLb  = SM_AL  + (wm * 16 + g) * AROW + tg * 4;
    const int bgH0 = SM_WGH + (wn * 16 + g) * WROW + tg * 4;
    const int bgH1 = SM_WGH + (wn * 16 + 8 + g) * WROW + tg * 4;
    const int bgL0 = SM_WGL + (wn * 16 + g) * WROW + tg * 4;
    const int bgL1 = SM_WGL + (wn * 16 + 8 + g) * WROW + tg * 4;
    const int bhH  = SM_WHH + (wn * 8 + g) * WROW + tg * 4;
    const int bhL  = SM_WHL + (wn * 8 + g) * WROW + tg * 4;

    const int r0 = mt * 32 + wm * 16 + g;

    for (int t = 0; t < S_; t++) {
        // ===================== GATE PHASE =====================
        float cA0[4] = {0,0,0,0}, cB0[4] = {0,0,0,0}, cC0[4] = {0,0,0,0};
        float cA1[4] = {0,0,0,0}, cB1[4] = {0,0,0,0}, cC1[4] = {0,0,0,0};
        uint4 ph0 = __ldcg((const uint4*)(hhrow));
        uint4 ph1 = __ldcg((const uint4*)(hhrow + 4));
        uint4 pl0 = __ldcg((const uint4*)(hlrow));
        uint4 pl1 = __ldcg((const uint4*)(hlrow + 4));

        #pragma unroll 1
        for (int c = 0; c < 4; c++) {
            *(uint4*)(stsH)      = ph0;
            *(uint4*)(stsH + 16) = ph1;
            *(uint4*)(stsL)      = pl0;
            *(uint4*)(stsL + 16) = pl1;
            __syncthreads();
            if (c < 3) {
                ph0 = __ldcg((const uint4*)(hhrow + (c + 1) * 64));
                ph1 = __ldcg((const uint4*)(hhrow + (c + 1) * 64 + 4));
                pl0 = __ldcg((const uint4*)(hlrow + (c + 1) * 64));
                pl1 = __ldcg((const uint4*)(hlrow + (c + 1) * 64 + 4));
            }
            const int kwb = c * 256;
            #pragma unroll
            for (int s = 0; s < 8; s++) {
                const int ka = s * 32;
                const int kw = kwb + s * 32;
                unsigned aH0 = *(const unsigned*)(smc + aHb + ka);
                unsigned aH1 = *(const unsigned*)(smc + aHb + 8 * AROW + ka);
                unsigned aH2 = *(const unsigned*)(smc + aHb + ka + 16);
                unsigned aH3 = *(const unsigned*)(smc + aHb + 8 * AROW + ka + 16);
                unsigned aL0 = *(const unsigned*)(smc + aLb + ka);
                unsigned aL1 = *(const unsigned*)(smc + aLb + 8 * AROW + ka);
                unsigned aL2 = *(const unsigned*)(smc + aLb + ka + 16);
                unsigned aL3 = *(const unsigned*)(smc + aLb + 8 * AROW + ka + 16);
                unsigned b0h0 = *(const unsigned*)(smc + bgH0 + kw);
                unsigned b0h1 = *(const unsigned*)(smc + bgH0 + kw + 16);
                unsigned b0l0 = *(const unsigned*)(smc + bgL0 + kw);
                unsigned b0l1 = *(const unsigned*)(smc + bgL0 + kw + 16);
                unsigned b1h0 = *(const unsigned*)(smc + bgH1 + kw);
                unsigned b1h1 = *(const unsigned*)(smc + bgH1 + kw + 16);
                unsigned b1l0 = *(const unsigned*)(smc + bgL1 + kw);
                unsigned b1l1 = *(const unsigned*)(smc + bgL1 + kw + 16);
                mma16816(cA0, aH0, aH1, aH2, aH3, b0h0, b0h1);
                mma16816(cB0, aH0, aH1, aH2, aH3, b0l0, b0l1);
                mma16816(cC0, aL0, aL1, aL2, aL3, b0h0, b0h1);
                mma16816(cA1, aH0, aH1, aH2, aH3, b1h0, b1h1);
                mma16816(cB1, aH0, aH1, aH2, aH3, b1l0, b1l1);
                mma16816(cC1, aL0, aL1, aL2, aL3, b1h0, b1h1);
            }
            if (c < 3) __syncthreads();
        }
        // gate epilogue
        {
            const float* Gxt = g_Gx + (size_t)t * B_ * H2_;
            #pragma unroll
            for (int tile = 0; tile < 2; tile++) {
                float s0 = tile ? (cA1[0] + cB1[0] + cC1[0]) : (cA0[0] + cB0[0] + cC0[0]);
                float s1 = tile ? (cA1[1] + cB1[1] + cC1[1]) : (cA0[1] + cB0[1] + cC0[1]);
                float s2 = tile ? (cA1[2] + cB1[2] + cC1[2]) : (cA0[2] + cB0[2] + cC0[2]);
                float s3 = tile ? (cA1[3] + cB1[3] + cC1[3]) : (cA0[3] + cB0[3] + cC0[3]);
                int n = nt * 64 + wn * 16 + tile * 8 + tg * 2;
                float2 gx0 = __ldcg((const float2*)(Gxt + (size_t)r0 * H2_ + n));
                float2 gx1 = __ldcg((const float2*)(Gxt + (size_t)(r0 + 8) * H2_ + n));
                float v00 = sigm(s0 + gx0.x), v01 = sigm(s1 + gx0.y);
                float v10 = sigm(s2 + gx1.x), v11 = sigm(s3 + gx1.y);
                if (nt < 8) {
                    __stcg((float2*)(g_z + r0 * H_ + n), make_float2(v00, v01));
                    __stcg((float2*)(g_z + (r0 + 8) * H_ + n), make_float2(v10, v11));
                } else {
                    int n2 = n - H_;
                    float2 hv0 = __ldcg((const float2*)(g_h + r0 * H_ + n2));
                    float2 hv1 = __ldcg((const float2*)(g_h + (r0 + 8) * H_ + n2));
                    unsigned hw, lw;
                    cvt_pair(v00 * hv0.x, v01 * hv0.y, hw, lw);
                    __stcg(&g_rhh[r0 * 256 + (n2 >> 1)], hw);
                    __stcg(&g_rhl[r0 * 256 + (n2 >> 1)], lw);
                    cvt_pair(v10 * hv1.x, v11 * hv1.y, hw, lw);
                    __stcg(&g_rhh[(r0 + 8) * 256 + (n2 >> 1)], hw);
                    __stcg(&g_rhl[(r0 + 8) * 256 + (n2 >> 1)], lw);
                }
            }
        }
        group_sync(mt, tgt += 16);

        // ===================== CANDIDATE PHASE =====================
        float dA[4] = {0,0,0,0}, dB[4] = {0,0,0,0}, dC[4] = {0,0,0,0};
        ph0 = __ldcg((const uint4*)(rhhrow));
        ph1 = __ldcg((const uint4*)(rhhrow + 4));
        pl0 = __ldcg((const uint4*)(rhlrow));
        pl1 = __ldcg((const uint4*)(rhlrow + 4));

        #pragma unroll 1
        for (int c = 0; c < 4; c++) {
            *(uint4*)(stsH)      = ph0;
            *(uint4*)(stsH + 16) = ph1;
            *(uint4*)(stsL)      = pl0;
            *(uint4*)(stsL + 16) = pl1;
            __syncthreads();
            if (c < 3) {
                ph0 = __ldcg((const uint4*)(rhhrow + (c + 1) * 64));
                ph1 = __ldcg((const uint4*)(rhhrow + (c + 1) * 64 + 4));
                pl0 = __ldcg((const uint4*)(rhlrow + (c + 1) * 64));
                pl1 = __ldcg((const uint4*)(rhlrow + (c + 1) * 64 + 4));
            }
            const int kwb = c * 256;
            #pragma unroll
            for (int s = 0; s < 8; s++) {
                const int ka = s * 32;
                const int kw = kwb + s * 32;
                unsigned aH0 = *(const unsigned*)(smc + aHb + ka);
                unsigned aH1 = *(const unsigned*)(smc + aHb + 8 * AROW + ka);
                unsigned aH2 = *(const unsigned*)(smc + aHb + ka + 16);
                unsigned aH3 = *(const unsigned*)(smc + aHb + 8 * AROW + ka + 16);
                unsigned aL0 = *(const unsigned*)(smc + aLb + ka);
                unsigned aL1 = *(const unsigned*)(smc + aLb + 8 * AROW + ka);
                unsigned aL2 = *(const unsigned*)(smc + aLb + ka + 16);
                unsigned aL3 = *(const unsigned*)(smc + aLb + 8 * AROW + ka + 16);
                unsigned bh0 = *(const unsigned*)(smc + bhH + kw);
                unsigned bh1 = *(const unsigned*)(smc + bhH + kw + 16);
                unsigned bl0 = *(const unsigned*)(smc + bhL + kw);
                unsigned bl1 = *(const unsigned*)(smc + bhL + kw + 16);
                mma16816(dA, aH0, aH1, aH2, aH3, bh0, bh1);
                mma16816(dB, aH0, aH1, aH2, aH3, bl0, bl1);
                mma16816(dC, aL0, aL1, aL2, aL3, bh0, bh1);
            }
            if (c < 3) __syncthreads();
        }
        // candidate epilogue: h update + split stores (h, hall)
        {
            const float* Cxt = g_Cx + (size_t)t * B_ * H_;
            int n = nt * 32 + wn * 8 + tg * 2;
            #pragma unroll
            for (int rr = 0; rr < 2; rr++) {
                int r = r0 + rr * 8;
                size_t idx = (size_t)r * H_ + n;
                float2 cx  = __ldcg((const float2*)(Cxt + idx));
                float2 zz  = __ldcg((const float2*)(g_z + idx));
                float2 hh2 = __ldcg((const float2*)(g_h + idx));
                float c0 = tanh_fast(dA[rr * 2 + 0] + dB[rr * 2 + 0] + dC[rr * 2 + 0] + cx.x);
                float c1 = tanh_fast(dA[rr * 2 + 1] + dB[rr * 2 + 1] + dC[rr * 2 + 1] + cx.y);
                float2 hn = make_float2(fmaf(zz.x, c0 - hh2.x, hh2.x),
                                        fmaf(zz.y, c1 - hh2.y, hh2.y));
                __stcg((float2*)(g_h + idx), hn);
                unsigned hw, lw;
                cvt_pair(hn.x, hn.y, hw, lw);
                __stcg(&g_hh[r * 256 + (n >> 1)], hw);
                __stcg(&g_hl[r * 256 + (n >> 1)], lw);
                size_t hidx = ((size_t)t * B_ + r) * 256 + (n >> 1);
                __stcg(&g_hallh[hidx], hw);
                __stcg(&g_halll[hidx], lw);
            }
        }
        group_sync(mt, tgt += 16);
    }
}

// ---------------------------------------------------------------------------
__global__ void gather_embed(const int* __restrict__ x,
                             const float* __restrict__ emb) {
    if (blockIdx.x == 0 && threadIdx.x < 8 * 32)
        g_gcnt[threadIdx.x] = 0;   // reset group-barrier counters each launch
    int idx = blockIdx.x * 256 + threadIdx.x;
    int h4  = idx & (H_ / 4 - 1);
    int row = idx >> 7;
    int b   = row & (B_ - 1);
    int s   = row >> 8;
    int tok = x[b * S_ + s];
    float4 v = reinterpret_cast<const float4*>(emb)[(size_t)tok * (H_ / 4) + h4];
    unsigned h0, l0, h1, l1;
    cvt_pair(v.x, v.y, h0, l0);
    cvt_pair(v.z, v.w, h1, l1);
    *(uint2*)&g_xeh[(size_t)row * 256 + h4 * 2] = make_uint2(h0, h1);
    *(uint2*)&g_xel[(size_t)row * 256 + h4 * 2] = make_uint2(l0, l1);
}

__global__ void copy_hfinal(float* __restrict__ out) {
    int i = blockIdx.x * 256 + threadIdx.x;
    out[i] = g_h[i];
}

// ---------------------------------------------------------------------------
extern "C" void kernel_launch(void* const* d_in, const int* in_sizes, int n_in,
                              void* d_out, int out_size) {
    (void)in_sizes; (void)n_in; (void)out_size;
    const int*   x   = (const int*)  d_in[0];
    const float* emb = (const float*)d_in[1];
    const float* Wg  = (const float*)d_in[2];
    const float* bg  = (const float*)d_in[3];
    const float* Wh  = (const float*)d_in[4];
    const float* bh  = (const float*)d_in[5];
    const float* Wo  = (const float*)d_in[6];
    const float* bo  = (const float*)d_in[7];
    float* out = (float*)d_out;

    static int smem_set = 0;
    if (!smem_set) {
        cudaFuncSetAttribute(gru_persist,
                             cudaFuncAttributeMaxDynamicSharedMemorySize,
                             GRU_SMEM);
        smem_set = 1;
    }

    gather_embed<<<(S_ * B_ * (H_ / 4)) / 256, 256>>>(x, emb);
    split_weights<<<1024, 256>>>(Wg, Wh, Wo);

    sgemm_tc2<<<dim3(H2_ / 128, 65536 / 128), 256>>>(0, 0, bg, 0, nullptr);
    sgemm_tc2<<<dim3(H_  / 128, 65536 / 128), 256>>>(0, 1, bh, 1, nullptr);

    gru_persist<<<128, 256, GRU_SMEM>>>(Wg, Wh);

    sgemm_tc2<<<dim3(O_ / 128, 65536 / 128), 256>>>(1, 2, bo, 2,
                                                    out + (size_t)B_ * H_);
    copy_hfinal<<<(B_ * H_) / 256, 256>>>(out);
}

// round 15
// speedup vs baseline: 1.3230x; 1.3230x over previous
#include <cuda_runtime.h>
#include <math.h>
#include <stdint.h>

// Problem constants
#define B_  256
#define S_  256
#define H_  512
#define H2_ 1024
#define O_  512

// ---------------------------------------------------------------------------
// Scratch (device globals)
// ---------------------------------------------------------------------------
__device__ float g_Gx  [(size_t)S_ * B_ * H2_];
__device__ float g_Cx  [(size_t)S_ * B_ * H_ ];
__device__ float g_hall[(size_t)S_ * B_ * H_ ];
__device__ float g_h   [B_ * H_];
__device__ float g_z   [B_ * H_];
__device__ float g_rh  [B_ * H_];

// pre-split bf16 hi/lo (packed pairs) for the pre-GEMMs
__device__ unsigned g_xeh[(size_t)S_ * B_ * H_ / 2];
__device__ unsigned g_xel[(size_t)S_ * B_ * H_ / 2];
__device__ unsigned g_Wgh[1024 * 256], g_Wgl[1024 * 256];   // Wg[:, :H]
__device__ unsigned g_Whh[512 * 256],  g_Whl[512 * 256];    // Wh[:, :H]

__device__ unsigned g_gcnt[8 * 32];   // group barrier counters (128B apart)

// ---------------------------------------------------------------------------
// helpers
// ---------------------------------------------------------------------------
__device__ __forceinline__ float sigm(float x) {
    return __fdividef(1.0f, 1.0f + __expf(-x));
}
__device__ __forceinline__ float tanh_fast(float x) {
    return 1.0f - 2.0f * __fdividef(1.0f, __expf(2.0f * x) + 1.0f);
}

// pack (f0,f1) -> bf16x2 hi word {lo=f0, hi=f1}; lo word = residuals
__device__ __forceinline__ void cvt_pair(float f0, float f1,
                                         unsigned& hi2, unsigned& lo2) {
    asm("cvt.rn.bf16x2.f32 %0, %2, %1;" : "=r"(hi2) : "f"(f0), "f"(f1));
    float h0 = __uint_as_float(hi2 << 16);
    float h1 = __uint_as_float(hi2 & 0xFFFF0000u);
    float l0 = f0 - h0, l1 = f1 - h1;
    asm("cvt.rn.bf16x2.f32 %0, %2, %1;" : "=r"(lo2) : "f"(l0), "f"(l1));
}

__device__ __forceinline__ void mma16816(float* c,
                                         unsigned a0, unsigned a1,
                                         unsigned a2, unsigned a3,
                                         unsigned b0, unsigned b1) {
    asm volatile(
        "mma.sync.aligned.m16n8k16.row.col.f32.bf16.bf16.f32 "
        "{%0,%1,%2,%3}, {%4,%5,%6,%7}, {%8,%9}, {%0,%1,%2,%3};"
        : "+f"(c[0]), "+f"(c[1]), "+f"(c[2]), "+f"(c[3])
        : "r"(a0), "r"(a1), "r"(a2), "r"(a3), "r"(b0), "r"(b1));
}

// ---------------------------------------------------------------------------
// Group barrier (16 blocks/group): REDG arrival + monotonic count wait
// ---------------------------------------------------------------------------
__device__ __forceinline__ void group_sync(int grp, unsigned target) {
    __threadfence();
    __syncthreads();
    if (threadIdx.x == 0) {
        unsigned* cp = &g_gcnt[grp * 32];
        asm volatile("red.global.gpu.add.u32 [%0], %1;"
                     :: "l"(cp), "r"(1u) : "memory");
        unsigned v;
        do {
            asm volatile("ld.acquire.gpu.u32 %0, [%1];" : "=r"(v) : "l"(cp));
        } while (v < target);
    }
    __syncthreads();
}

// ---------------------------------------------------------------------------
// split_weights: one-shot fp32 -> bf16 hi/lo for Wg[:, :H] and Wh[:, :H]
// rows: [0,1024) Wg; [1024,1536) Wh
// ---------------------------------------------------------------------------
__global__ void split_weights(const float* __restrict__ Wg,
                              const float* __restrict__ Wh) {
    int idx = blockIdx.x * 256 + threadIdx.x;   // 1536 * 128
    int rid = idx >> 7;
    int kq  = idx & 127;
    const float* src;
    unsigned *dh, *dl;
    if (rid < 1024) {
        src = Wg + (size_t)rid * H2_ + kq * 4;
        dh = g_Wgh + rid * 256 + kq * 2;  dl = g_Wgl + rid * 256 + kq * 2;
    } else {
        int r = rid - 1024;
        src = Wh + (size_t)r * H2_ + kq * 4;
        dh = g_Whh + r * 256 + kq * 2;    dl = g_Whl + r * 256 + kq * 2;
    }
    float4 v = *(const float4*)src;
    unsigned h0, l0, h1, l1;
    cvt_pair(v.x, v.y, h0, l0);
    cvt_pair(v.z, v.w, h1, l1);
    *(uint2*)dh = make_uint2(h0, h1);
    *(uint2*)dl = make_uint2(l0, l1);
}

// ---------------------------------------------------------------------------
// Pre-split tensor-core GEMM (R11 pipeline shape, conversion removed):
// C[65536,N] = A @ B^T + bias.  A/B are bf16 hi/lo global (256 uints/row).
// 128x128 block, 8 warps, 16-k chunks with register prefetch, ASTR=48.
// mode 0 -> g_Gx (B = Wg split), mode 1 -> g_Cx (B = Wh split).
// ---------------------------------------------------------------------------
#define ASTR 48

__global__ __launch_bounds__(256, 2)
void sgemm_ps(int Bsel, const float* __restrict__ bias, int mode) {
    __shared__ char sAH[128 * ASTR];
    __shared__ char sAL[128 * ASTR];
    __shared__ char sBH[128 * ASTR];
    __shared__ char sBL[128 * ASTR];

    const int tid  = threadIdx.x;
    const int wid  = tid >> 5;
    const int lane = tid & 31;
    const int g    = lane >> 2;
    const int tg   = lane & 3;
    const int wm   = wid >> 1;
    const int wn   = wid & 1;
    const int m0   = blockIdx.y * 128;
    const int n0   = blockIdx.x * 128;

    const unsigned* Bh = Bsel ? g_Whh : g_Wgh;
    const unsigned* Bl = Bsel ? g_Whl : g_Wgl;

    const int lr = tid >> 1;           // 0..127
    const int lh = tid & 1;            // k half of chunk (4 uints)
    const unsigned* Aph = g_xeh + (size_t)(m0 + lr) * 256 + lh * 4;
    const unsigned* Apl = g_xel + (size_t)(m0 + lr) * 256 + lh * 4;
    const unsigned* Bph = Bh + (size_t)(n0 + lr) * 256 + lh * 4;
    const unsigned* Bpl = Bl + (size_t)(n0 + lr) * 256 + lh * 4;
    const size_t dA = (size_t)(lr * ASTR + lh * 16);

    float c[2][8][4];
    #pragma unroll
    for (int i = 0; i < 2; i++)
        #pragma unroll
        for (int j = 0; j < 8; j++)
            #pragma unroll
            for (int q = 0; q < 4; q++) c[i][j][q] = 0.f;

    uint4 pah = *(const uint4*)(Aph);
    uint4 pal = *(const uint4*)(Apl);
    uint4 pbh = *(const uint4*)(Bph);
    uint4 pbl = *(const uint4*)(Bpl);

    #pragma unroll 1
    for (int it = 0; it < 32; it++) {
        *(uint4*)(sAH + dA) = pah;
        *(uint4*)(sAL + dA) = pal;
        *(uint4*)(sBH + dA) = pbh;
        *(uint4*)(sBL + dA) = pbl;
        __syncthreads();
        if (it < 31) {
            pah = *(const uint4*)(Aph + (it + 1) * 8);
            pal = *(const uint4*)(Apl + (it + 1) * 8);
            pbh = *(const uint4*)(Bph + (it + 1) * 8);
            pbl = *(const uint4*)(Bpl + (it + 1) * 8);
        }
        unsigned aH[2][4], aL[2][4];
        #pragma unroll
        for (int mt = 0; mt < 2; mt++) {
            int ab = (wm * 32 + mt * 16 + g) * ASTR + tg * 4;
            aH[mt][0] = *(const unsigned*)(sAH + ab);
            aH[mt][1] = *(const unsigned*)(sAH + ab + 8 * ASTR);
            aH[mt][2] = *(const unsigned*)(sAH + ab + 16);
            aH[mt][3] = *(const unsigned*)(sAH + ab + 8 * ASTR + 16);
            aL[mt][0] = *(const unsigned*)(sAL + ab);
            aL[mt][1] = *(const unsigned*)(sAL + ab + 8 * ASTR);
            aL[mt][2] = *(const unsigned*)(sAL + ab + 16);
            aL[mt][3] = *(const unsigned*)(sAL + ab + 8 * ASTR + 16);
        }
        #pragma unroll
        for (int nt2 = 0; nt2 < 8; nt2++) {
            int nb = (wn * 64 + nt2 * 8 + g) * ASTR + tg * 4;
            unsigned bh0 = *(const unsigned*)(sBH + nb);
            unsigned bh1 = *(const unsigned*)(sBH + nb + 16);
            unsigned bl0 = *(const unsigned*)(sBL + nb);
            unsigned bl1 = *(const unsigned*)(sBL + nb + 16);
            #pragma unroll
            for (int mt = 0; mt < 2; mt++) {
                mma16816(c[mt][nt2], aH[mt][0], aH[mt][1], aH[mt][2], aH[mt][3], bh0, bh1);
                mma16816(c[mt][nt2], aH[mt][0], aH[mt][1], aH[mt][2], aH[mt][3], bl0, bl1);
                mma16816(c[mt][nt2], aL[mt][0], aL[mt][1], aL[mt][2], aL[mt][3], bh0, bh1);
            }
        }
        __syncthreads();
    }

    #pragma unroll
    for (int mt = 0; mt < 2; mt++) {
        int row0 = m0 + wm * 32 + mt * 16 + g;
        int row1 = row0 + 8;
        #pragma unroll
        for (int nt2 = 0; nt2 < 8; nt2++) {
            int n = n0 + wn * 64 + nt2 * 8 + tg * 2;
            float2 bv = *(const float2*)(bias + n);
            float o00 = c[mt][nt2][0] + bv.x, o01 = c[mt][nt2][1] + bv.y;
            float o10 = c[mt][nt2][2] + bv.x, o11 = c[mt][nt2][3] + bv.y;
            if (mode == 0) {
                *(float2*)(g_Gx + (size_t)row0 * H2_ + n) = make_float2(o00, o01);
                *(float2*)(g_Gx + (size_t)row1 * H2_ + n) = make_float2(o10, o11);
            } else {
                *(float2*)(g_Cx + (size_t)row0 * H_ + n) = make_float2(o00, o01);
                *(float2*)(g_Cx + (size_t)row1 * H_ + n) = make_float2(o10, o11);
            }
        }
    }
}

// ---------------------------------------------------------------------------
// R11 tensor-core GEMM (convert-on-fly) — used for the ys projection only:
// yout = hall @ Wo^T + bo  (A = g_hall fp32, B = Wo fp32)
// ---------------------------------------------------------------------------
__global__ __launch_bounds__(256, 2)
void sgemm_tc(const float* __restrict__ Bw, int ldb,
              const float* __restrict__ bias,
              float* __restrict__ yout) {
    __shared__ char sAH[128 * ASTR];
    __shared__ char sAL[128 * ASTR];
    __shared__ char sBH[128 * ASTR];
    __shared__ char sBL[128 * ASTR];

    const int tid  = threadIdx.x;
    const int wid  = tid >> 5;
    const int lane = tid & 31;
    const int g    = lane >> 2;
    const int tg   = lane & 3;
    const int wm   = wid >> 1;
    const int wn   = wid & 1;
    const int m0   = blockIdx.y * 128;
    const int n0   = blockIdx.x * 128;

    const int lr = tid >> 1;
    const int lh = tid & 1;
    const float* Ap = g_hall + (size_t)(m0 + lr) * H_ + lh * 8;
    const float* Bp = Bw + (size_t)(n0 + lr) * ldb + lh * 8;

    float c[2][8][4];
    #pragma unroll
    for (int i = 0; i < 2; i++)
        #pragma unroll
        for (int j = 0; j < 8; j++)
            #pragma unroll
            for (int q = 0; q < 4; q++) c[i][j][q] = 0.f;

    float4 pa0 = *(const float4*)(Ap);
    float4 pa1 = *(const float4*)(Ap + 4);
    float4 pb0 = *(const float4*)(Bp);
    float4 pb1 = *(const float4*)(Bp + 4);

    #pragma unroll 1
    for (int k0 = 0; k0 < H_; k0 += 16) {
        {
            unsigned h0, l0, h1, l1, h2, l2, h3, l3;
            cvt_pair(pa0.x, pa0.y, h0, l0); cvt_pair(pa0.z, pa0.w, h1, l1);
            cvt_pair(pa1.x, pa1.y, h2, l2); cvt_pair(pa1.z, pa1.w, h3, l3);
            size_t dA = (size_t)(lr * ASTR + lh * 16);
            *(uint2*)(sAH + dA)     = make_uint2(h0, h1);
            *(uint2*)(sAH + dA + 8) = make_uint2(h2, h3);
            *(uint2*)(sAL + dA)     = make_uint2(l0, l1);
            *(uint2*)(sAL + dA + 8) = make_uint2(l2, l3);
            cvt_pair(pb0.x, pb0.y, h0, l0); cvt_pair(pb0.z, pb0.w, h1, l1);
            cvt_pair(pb1.x, pb1.y, h2, l2); cvt_pair(pb1.z, pb1.w, h3, l3);
            *(uint2*)(sBH + dA)     = make_uint2(h0, h1);
            *(uint2*)(sBH + dA + 8) = make_uint2(h2, h3);
            *(uint2*)(sBL + dA)     = make_uint2(l0, l1);
            *(uint2*)(sBL + dA + 8) = make_uint2(l2, l3);
        }
        __syncthreads();
        if (k0 < H_ - 16) {
            pa0 = *(const float4*)(Ap + k0 + 16);
            pa1 = *(const float4*)(Ap + k0 + 20);
            pb0 = *(const float4*)(Bp + k0 + 16);
            pb1 = *(const float4*)(Bp + k0 + 20);
        }
        unsigned aH[2][4], aL[2][4];
        #pragma unroll
        for (int mt = 0; mt < 2; mt++) {
            int ab = (wm * 32 + mt * 16 + g) * ASTR + tg * 4;
            aH[mt][0] = *(const unsigned*)(sAH + ab);
            aH[mt][1] = *(const unsigned*)(sAH + ab + 8 * ASTR);
            aH[mt][2] = *(const unsigned*)(sAH + ab + 16);
            aH[mt][3] = *(const unsigned*)(sAH + ab + 8 * ASTR + 16);
            aL[mt][0] = *(const unsigned*)(sAL + ab);
            aL[mt][1] = *(const unsigned*)(sAL + ab + 8 * ASTR);
            aL[mt][2] = *(const unsigned*)(sAL + ab + 16);
            aL[mt][3] = *(const unsigned*)(sAL + ab + 8 * ASTR + 16);
        }
        #pragma unroll
        for (int nt2 = 0; nt2 < 8; nt2++) {
            int nb = (wn * 64 + nt2 * 8 + g) * ASTR + tg * 4;
            unsigned bh0 = *(const unsigned*)(sBH + nb);
            unsigned bh1 = *(const unsigned*)(sBH + nb + 16);
            unsigned bl0 = *(const unsigned*)(sBL + nb);
            unsigned bl1 = *(const unsigned*)(sBL + nb + 16);
            #pragma unroll
            for (int mt = 0; mt < 2; mt++) {
                mma16816(c[mt][nt2], aH[mt][0], aH[mt][1], aH[mt][2], aH[mt][3], bh0, bh1);
                mma16816(c[mt][nt2], aH[mt][0], aH[mt][1], aH[mt][2], aH[mt][3], bl0, bl1);
                mma16816(c[mt][nt2], aL[mt][0], aL[mt][1], aL[mt][2], aL[mt][3], bh0, bh1);
            }
        }
        __syncthreads();
    }

    #pragma unroll
    for (int mt = 0; mt < 2; mt++) {
        int row0 = m0 + wm * 32 + mt * 16 + g;
        int row1 = row0 + 8;
        #pragma unroll
        for (int nt2 = 0; nt2 < 8; nt2++) {
            int n = n0 + wn * 64 + nt2 * 8 + tg * 2;
            float2 bv = *(const float2*)(bias + n);
            float o00 = c[mt][nt2][0] + bv.x, o01 = c[mt][nt2][1] + bv.y;
            float o10 = c[mt][nt2][2] + bv.x, o11 = c[mt][nt2][3] + bv.y;
            int s0 = row0 >> 8, b0i = row0 & 255;
            int s1 = row1 >> 8, b1i = row1 & 255;
            *(float2*)(yout + ((size_t)b0i * S_ + s0) * O_ + n) = make_float2(o00, o01);
            *(float2*)(yout + ((size_t)b1i * S_ + s1) * O_ + n) = make_float2(o10, o11);
        }
    }
}

// ---------------------------------------------------------------------------
// Persistent recurrent kernel — R11 VERBATIM (proven 3.65 ms):
// 128 blocks x 256 threads (8 warps), group-of-16 barriers.
//   gate: m [mt*32,+32) x n [nt*64,+64) of 1024; warp = m16 x n16
//   cand: m [mt*32,+32) x n [nt*32,+32) of 512;  warp = m16 x n8
// ---------------------------------------------------------------------------
#define WROW 1040
#define AROW 272
#define SM_WGH 0
#define SM_WGL (SM_WGH + 64 * WROW)
#define SM_WHH (SM_WGL + 64 * WROW)
#define SM_WHL (SM_WHH + 32 * WROW)
#define SM_AH  (SM_WHL + 32 * WROW)
#define SM_AL  (SM_AH + 32 * AROW)
#define GRU_SMEM (SM_AL + 32 * AROW)    // 217088 bytes

__global__ __launch_bounds__(256, 1)
void gru_persist(const float* __restrict__ Wg, const float* __restrict__ Wh) {
    extern __shared__ char smc[];

    const int tid  = threadIdx.x;
    const int bid  = blockIdx.x;
    const int mt   = bid >> 4;
    const int nt   = bid & 15;
    const int wid  = tid >> 5;
    const int lane = tid & 31;
    const int wm   = wid >> 2;
    const int wn   = wid & 3;
    const int g    = lane >> 2;
    const int tg   = lane & 3;

    {
        int base = (bid * 256 + tid) * 4;
        *(float4*)&g_h[base] = make_float4(0.f, 0.f, 0.f, 0.f);
    }

    {   // Wg: 64 rows (nt*64+j), k in [512,1024)
        int j  = tid >> 2;
        int ks = (tid & 3) * 128;
        const float* src = Wg + (size_t)(nt * 64 + j) * H2_ + H_ + ks;
        char* dh = smc + SM_WGH + j * WROW + ks * 2;
        char* dl = smc + SM_WGL + j * WROW + ks * 2;
        #pragma unroll 8
        for (int q = 0; q < 32; q++) {
            float4 v = *(const float4*)(src + q * 4);
            unsigned h0, l0, h1, l1;
            cvt_pair(v.x, v.y, h0, l0);
            cvt_pair(v.z, v.w, h1, l1);
            *(uint2*)(dh + q * 8) = make_uint2(h0, h1);
            *(uint2*)(dl + q * 8) = make_uint2(l0, l1);
        }
    }
    {   // Wh: 32 rows (nt*32+j), k in [512,1024)
        int j  = tid >> 3;
        int ks = (tid & 7) * 64;
        const float* src = Wh + (size_t)(nt * 32 + j) * H2_ + H_ + ks;
        char* dh = smc + SM_WHH + j * WROW + ks * 2;
        char* dl = smc + SM_WHL + j * WROW + ks * 2;
        #pragma unroll 8
        for (int q = 0; q < 16; q++) {
            float4 v = *(const float4*)(src + q * 4);
            unsigned h0, l0, h1, l1;
            cvt_pair(v.x, v.y, h0, l0);
            cvt_pair(v.z, v.w, h1, l1);
            *(uint2*)(dh + q * 8) = make_uint2(h0, h1);
            *(uint2*)(dl + q * 8) = make_uint2(l0, l1);
        }
    }
    unsigned tgt = 0;
    group_sync(mt, tgt += 16);

    const float* hrow  = g_h  + (size_t)mt * 32 * H_;
    const float* rhrow = g_rh + (size_t)mt * 32 * H_;

    const int pr  = tid >> 3;
    const int pks = (tid & 7) * 16;

    const int aHb = SM_AH + (wm * 16 + g) * AROW + tg * 4;
    const int aLb = SM_AL + (wm * 16 + g) * AROW + tg * 4;
    const int bgH0 = SM_WGH + (wn * 16 + g) * WROW + tg * 4;
    const int bgH1 = SM_WGH + (wn * 16 + 8 + g) * WROW + tg * 4;
    const int bgL0 = SM_WGL + (wn * 16 + g) * WROW + tg * 4;
    const int bgL1 = SM_WGL + (wn * 16 + 8 + g) * WROW + tg * 4;
    const int bhH  = SM_WHH + (wn * 8 + g) * WROW + tg * 4;
    const int bhL  = SM_WHL + (wn * 8 + g) * WROW + tg * 4;

    const int r0 = mt * 32 + wm * 16 + g;

    for (int t = 0; t < S_; t++) {
        // ===================== GATE PHASE =====================
        float cg0[4] = {0.f, 0.f, 0.f, 0.f};
        float cg1[4] = {0.f, 0.f, 0.f, 0.f};
        float4 pf[4];
        #pragma unroll
        for (int q = 0; q < 4; q++)
            pf[q] = __ldcg((const float4*)(hrow + (size_t)pr * H_ + pks + q * 4));

        #pragma unroll 1
        for (int c = 0; c < 4; c++) {
            {
                char* dh = smc + SM_AH + pr * AROW + pks * 2;
                char* dl = smc + SM_AL + pr * AROW + pks * 2;
                #pragma unroll
                for (int q = 0; q < 4; q++) {
                    unsigned h0, l0, h1, l1;
                    cvt_pair(pf[q].x, pf[q].y, h0, l0);
                    cvt_pair(pf[q].z, pf[q].w, h1, l1);
                    *(uint2*)(dh + q * 8) = make_uint2(h0, h1);
                    *(uint2*)(dl + q * 8) = make_uint2(l0, l1);
                }
            }
            __syncthreads();
            if (c < 3) {
                #pragma unroll
                for (int q = 0; q < 4; q++)
                    pf[q] = __ldcg((const float4*)(hrow + (size_t)pr * H_
                                                   + (c + 1) * 128 + pks + q * 4));
            }
            const int kwb = c * 256;
            #pragma unroll
            for (int s = 0; s < 8; s++) {
                const int ka = s * 32;
                const int kw = kwb + s * 32;
                unsigned aH0 = *(const unsigned*)(smc + aHb + ka);
                unsigned aH1 = *(const unsigned*)(smc + aHb + 8 * AROW + ka);
                unsigned aH2 = *(const unsigned*)(smc + aHb + ka + 16);
                unsigned aH3 = *(const unsigned*)(smc + aHb + 8 * AROW + ka + 16);
                unsigned aL0 = *(const unsigned*)(smc + aLb + ka);
                unsigned aL1 = *(const unsigned*)(smc + aLb + 8 * AROW + ka);
                unsigned aL2 = *(const unsigned*)(smc + aLb + ka + 16);
                unsigned aL3 = *(const unsigned*)(smc + aLb + 8 * AROW + ka + 16);
                unsigned b0h0 = *(const unsigned*)(smc + bgH0 + kw);
                unsigned b0h1 = *(const unsigned*)(smc + bgH0 + kw + 16);
                unsigned b0l0 = *(const unsigned*)(smc + bgL0 + kw);
                unsigned b0l1 = *(const unsigned*)(smc + bgL0 + kw + 16);
                unsigned b1h0 = *(const unsigned*)(smc + bgH1 + kw);
                unsigned b1h1 = *(const unsigned*)(smc + bgH1 + kw + 16);
                unsigned b1l0 = *(const unsigned*)(smc + bgL1 + kw);
                unsigned b1l1 = *(const unsigned*)(smc + bgL1 + kw + 16);
                mma16816(cg0, aH0, aH1, aH2, aH3, b0h0, b0h1);
                mma16816(cg0, aH0, aH1, aH2, aH3, b0l0, b0l1);
                mma16816(cg0, aL0, aL1, aL2, aL3, b0h0, b0h1);
                mma16816(cg1, aH0, aH1, aH2, aH3, b1h0, b1h1);
                mma16816(cg1, aH0, aH1, aH2, aH3, b1l0, b1l1);
                mma16816(cg1, aL0, aL1, aL2, aL3, b1h0, b1h1);
            }
            if (c < 3) __syncthreads();
        }
        {
            const float* Gxt = g_Gx + (size_t)t * B_ * H2_;
            #pragma unroll
            for (int tile = 0; tile < 2; tile++) {
                float* cc = tile ? cg1 : cg0;
                int n = nt * 64 + wn * 16 + tile * 8 + tg * 2;
                float2 gx0 = __ldcg((const float2*)(Gxt + (size_t)r0 * H2_ + n));
                float2 gx1 = __ldcg((const float2*)(Gxt + (size_t)(r0 + 8) * H2_ + n));
                float v00 = sigm(cc[0] + gx0.x), v01 = sigm(cc[1] + gx0.y);
                float v10 = sigm(cc[2] + gx1.x), v11 = sigm(cc[3] + gx1.y);
                if (nt < 8) {
                    __stcg((float2*)(g_z + r0 * H_ + n), make_float2(v00, v01));
                    __stcg((float2*)(g_z + (r0 + 8) * H_ + n), make_float2(v10, v11));
                } else {
                    int n2 = n - H_;
                    float2 hv0 = __ldcg((const float2*)(g_h + r0 * H_ + n2));
                    float2 hv1 = __ldcg((const float2*)(g_h + (r0 + 8) * H_ + n2));
                    __stcg((float2*)(g_rh + r0 * H_ + n2),
                           make_float2(v00 * hv0.x, v01 * hv0.y));
                    __stcg((float2*)(g_rh + (r0 + 8) * H_ + n2),
                           make_float2(v10 * hv1.x, v11 * hv1.y));
                }
            }
        }
        group_sync(mt, tgt += 16);

        // ===================== CANDIDATE PHASE =====================
        float cc[4] = {0.f, 0.f, 0.f, 0.f};
        #pragma unroll
        for (int q = 0; q < 4; q++)
            pf[q] = __ldcg((const float4*)(rhrow + (size_t)pr * H_ + pks + q * 4));

        #pragma unroll 1
        for (int c = 0; c < 4; c++) {
            {
                char* dh = smc + SM_AH + pr * AROW + pks * 2;
                char* dl = smc + SM_AL + pr * AROW + pks * 2;
                #pragma unroll
                for (int q = 0; q < 4; q++) {
                    unsigned h0, l0, h1, l1;
                    cvt_pair(pf[q].x, pf[q].y, h0, l0);
                    cvt_pair(pf[q].z, pf[q].w, h1, l1);
                    *(uint2*)(dh + q * 8) = make_uint2(h0, h1);
                    *(uint2*)(dl + q * 8) = make_uint2(l0, l1);
                }
            }
            __syncthreads();
            if (c < 3) {
                #pragma unroll
                for (int q = 0; q < 4; q++)
                    pf[q] = __ldcg((const float4*)(rhrow + (size_t)pr * H_
                                                   + (c + 1) * 128 + pks + q * 4));
            }
            const int kwb = c * 256;
            #pragma unroll
            for (int s = 0; s < 8; s++) {
                const int ka = s * 32;
                const int kw = kwb + s * 32;
                unsigned aH0 = *(const unsigned*)(smc + aHb + ka);
                unsigned aH1 = *(const unsigned*)(smc + aHb + 8 * AROW + ka);
                unsigned aH2 = *(const unsigned*)(smc + aHb + ka + 16);
                unsigned aH3 = *(const unsigned*)(smc + aHb + 8 * AROW + ka + 16);
                unsigned aL0 = *(const unsigned*)(smc + aLb + ka);
                unsigned aL1 = *(const unsigned*)(smc + aLb + 8 * AROW + ka);
                unsigned aL2 = *(const unsigned*)(smc + aLb + ka + 16);
                unsigned aL3 = *(const unsigned*)(smc + aLb + 8 * AROW + ka + 16);
                unsigned bh0 = *(const unsigned*)(smc + bhH + kw);
                unsigned bh1 = *(const unsigned*)(smc + bhH + kw + 16);
                unsigned bl0 = *(const unsigned*)(smc + bhL + kw);
                unsigned bl1 = *(const unsigned*)(smc + bhL + kw + 16);
                mma16816(cc, aH0, aH1, aH2, aH3, bh0, bh1);
                mma16816(cc, aH0, aH1, aH2, aH3, bl0, bl1);
                mma16816(cc, aL0, aL1, aL2, aL3, bh0, bh1);
            }
            if (c < 3) __syncthreads();
        }
        {
            float* hall_t = g_hall + (size_t)t * B_ * H_;
            const float* Cxt = g_Cx + (size_t)t * B_ * H_;
            int n = nt * 32 + wn * 8 + tg * 2;
            #pragma unroll
            for (int rr = 0; rr < 2; rr++) {
                int r = r0 + rr * 8;
                size_t idx = (size_t)r * H_ + n;
                float2 cx = __ldcg((const float2*)(Cxt + idx));
                float2 zz = __ldcg((const float2*)(g_z + idx));
                float2 hh = __ldcg((const float2*)(g_h + idx));
                float c0 = tanh_fast(cc[rr * 2 + 0] + cx.x);
                float c1 = tanh_fast(cc[rr * 2 + 1] + cx.y);
                float2 hn = make_float2(fmaf(zz.x, c0 - hh.x, hh.x),
                                        fmaf(zz.y, c1 - hh.y, hh.y));
                __stcg((float2*)(g_h + idx), hn);
                __stcg((float2*)(hall_t + idx), hn);
            }
        }
        group_sync(mt, tgt += 16);
    }
}

// ---------------------------------------------------------------------------
__global__ void gather_embed(const int* __restrict__ x,
                             const float* __restrict__ emb) {
    if (blockIdx.x == 0 && threadIdx.x < 8 * 32)
        g_gcnt[threadIdx.x] = 0;   // reset group-barrier counters each launch
    int idx = blockIdx.x * 256 + threadIdx.x;
    int h4  = idx & (H_ / 4 - 1);
    int row = idx >> 7;
    int b   = row & (B_ - 1);
    int s   = row >> 8;
    int tok = x[b * S_ + s];
    float4 v = reinterpret_cast<const float4*>(emb)[(size_t)tok * (H_ / 4) + h4];
    unsigned h0, l0, h1, l1;
    cvt_pair(v.x, v.y, h0, l0);
    cvt_pair(v.z, v.w, h1, l1);
    *(uint2*)&g_xeh[(size_t)row * 256 + h4 * 2] = make_uint2(h0, h1);
    *(uint2*)&g_xel[(size_t)row * 256 + h4 * 2] = make_uint2(l0, l1);
}

__global__ void copy_hfinal(float* __restrict__ out) {
    int i = blockIdx.x * 256 + threadIdx.x;
    out[i] = g_h[i];
}

// ---------------------------------------------------------------------------
extern "C" void kernel_launch(void* const* d_in, const int* in_sizes, int n_in,
                              void* d_out, int out_size) {
    (void)in_sizes; (void)n_in; (void)out_size;
    const int*   x   = (const int*)  d_in[0];
    const float* emb = (const float*)d_in[1];
    const float* Wg  = (const float*)d_in[2];
    const float* bg  = (const float*)d_in[3];
    const float* Wh  = (const float*)d_in[4];
    const float* bh  = (const float*)d_in[5];
    const float* Wo  = (const float*)d_in[6];
    const float* bo  = (const float*)d_in[7];
    float* out = (float*)d_out;

    static int smem_set = 0;
    if (!smem_set) {
        cudaFuncSetAttribute(gru_persist,
                             cudaFuncAttributeMaxDynamicSharedMemorySize,
                             GRU_SMEM);
        smem_set = 1;
    }

    gather_embed<<<(S_ * B_ * (H_ / 4)) / 256, 256>>>(x, emb);
    split_weights<<<768, 256>>>(Wg, Wh);

    sgemm_ps<<<dim3(H2_ / 128, 65536 / 128), 256>>>(0, bg, 0);
    sgemm_ps<<<dim3(H_  / 128, 65536 / 128), 256>>>(1, bh, 1);

    gru_persist<<<128, 256, GRU_SMEM>>>(Wg, Wh);

    sgemm_tc<<<dim3(O_ / 128, 65536 / 128), 256>>>(Wo, H_, bo,
                                                   out + (size_t)B_ * H_);
    copy_hfinal<<<(B_ * H_) / 256, 256>>>(out);
}